// round 1
// baseline (speedup 1.0000x reference)
#include <cuda_runtime.h>
#include <math.h>

// Problem constants
#define BB 2
#define SS 2048
#define DD 1024
#define NH 16
#define NKV 4
#define DH 64
#define MM (BB*SS)   // 4096

// ---------------- scratch (static device globals; no allocation) ----------------
__device__ float g_q [MM * DD];        // q proj  [4096,1024]
__device__ float g_k [MM * NKV*DH];    // k proj  [4096,256]
__device__ float g_v [MM * NKV*DH];    // v proj  [4096,256]
__device__ float g_qr[MM * DD];        // roped q
__device__ float g_kr[MM * NKV*DH];    // roped k
__device__ float g_ao[MM * DD];        // attention output [4096,1024]

// ---------------- generic SGEMM: C[M,N] = A[M,K] @ B[K,N] + bias ----------------
// BM=BN=128, BK=16, 256 threads, 8x8 microtile with split fragments.
#define GBM 128
#define GBN 128
#define GBK 16

__global__ __launch_bounds__(256, 2)
void sgemm_bias(const float* __restrict__ A, const float* __restrict__ B,
                const float* __restrict__ bias, float* __restrict__ C,
                int M, int N, int K)
{
    __shared__ float As[GBK][GBM];
    __shared__ float Bs[GBK][GBN];

    const int tid = threadIdx.x;
    const int tx  = tid & 15;
    const int ty  = tid >> 4;
    const int bm  = blockIdx.y * GBM;
    const int bn  = blockIdx.x * GBN;

    float acc[8][8];
#pragma unroll
    for (int i = 0; i < 8; i++)
#pragma unroll
        for (int j = 0; j < 8; j++) acc[i][j] = 0.f;

    const float* Ag = A + (size_t)bm * K;
    const float* Bg = B + bn;

    for (int k0 = 0; k0 < K; k0 += GBK) {
        // A tile: 128x16 = 512 float4, 2 per thread; store transposed
#pragma unroll
        for (int it = 0; it < 2; it++) {
            int f  = tid + it * 256;
            int m  = f >> 2;
            int kk = (f & 3) << 2;
            float4 v = *(const float4*)(Ag + (size_t)m * K + k0 + kk);
            As[kk + 0][m] = v.x; As[kk + 1][m] = v.y;
            As[kk + 2][m] = v.z; As[kk + 3][m] = v.w;
        }
        // B tile: 16x128
#pragma unroll
        for (int it = 0; it < 2; it++) {
            int f  = tid + it * 256;
            int kk = f >> 5;
            int n  = (f & 31) << 2;
            *(float4*)(&Bs[kk][n]) = *(const float4*)(Bg + (size_t)(k0 + kk) * N + n);
        }
        __syncthreads();

#pragma unroll
        for (int kk = 0; kk < GBK; kk++) {
            float a[8], b[8];
            *(float4*)(a)     = *(const float4*)(&As[kk][ty * 4]);
            *(float4*)(a + 4) = *(const float4*)(&As[kk][64 + ty * 4]);
            *(float4*)(b)     = *(const float4*)(&Bs[kk][tx * 4]);
            *(float4*)(b + 4) = *(const float4*)(&Bs[kk][64 + tx * 4]);
#pragma unroll
            for (int i = 0; i < 8; i++)
#pragma unroll
                for (int j = 0; j < 8; j++)
                    acc[i][j] += a[i] * b[j];
        }
        __syncthreads();
    }

#pragma unroll
    for (int i = 0; i < 8; i++) {
        int r = bm + ((i < 4) ? (ty * 4 + i) : (64 + ty * 4 + i - 4));
#pragma unroll
        for (int jv = 0; jv < 2; jv++) {
            int c = bn + ((jv == 0) ? (tx * 4) : (64 + tx * 4));
            float4 o;
            o.x = acc[i][jv * 4 + 0] + bias[c + 0];
            o.y = acc[i][jv * 4 + 1] + bias[c + 1];
            o.z = acc[i][jv * 4 + 2] + bias[c + 2];
            o.w = acc[i][jv * 4 + 3] + bias[c + 3];
            *(float4*)(&C[(size_t)r * N + c]) = o;
        }
    }
}

// ---------------- RoPE: half-split rotation per head ----------------
__global__ void rope_kernel(const float* __restrict__ in, float* __restrict__ out,
                            int nHeads)
{
    int idx = blockIdx.x * blockDim.x + threadIdx.x;
    int total = MM * nHeads * 32;
    if (idx >= total) return;
    int i   = idx & 31;
    int h   = (idx >> 5) % nHeads;
    int row = idx / (nHeads * 32);
    int s   = row & (SS - 1);

    float ex  = -(float)(2 * i) / 64.0f;
    float inv = powf(10000.0f, ex);
    float ang = (float)s * inv;
    float sn, cs;
    sincosf(ang, &sn, &cs);

    int stride = nHeads * 64;
    const float* p = in  + (size_t)row * stride + h * 64;
    float*       q = out + (size_t)row * stride + h * 64;
    float x1 = p[i], x2 = p[i + 32];
    q[i]      = x1 * cs - x2 * sn;
    q[i + 32] = x1 * sn + x2 * cs;
}

// ---------------- flash attention: 64x64 tiles, streaming softmax ----------------
#define BQ 64
#define BKV 64
#define LW 68                                    // padded row width (floats)
#define ATTN_SMEM ((4 * BQ * LW + 64) * 4)       // Qs,Ks,Vs,Ps + mask bias

__global__ __launch_bounds__(256)
void attn_kernel(const float* __restrict__ Q,    // [4096,1024] roped
                 const float* __restrict__ Km,   // [4096,256]  roped
                 const float* __restrict__ Vm,   // [4096,256]
                 const float* __restrict__ mask, // [B,S]
                 float* __restrict__ O)          // [4096,1024]
{
    extern __shared__ float sm[];
    float* Qs = sm;
    float* Ks = Qs + BQ * LW;
    float* Vs = Ks + BKV * LW;
    float* Ps = Vs + BKV * LW;
    float* Ms = Ps + BQ * LW;

    const int qb = blockIdx.x, h = blockIdx.y, b = blockIdx.z;
    const int kv = h >> 2;     // rep = NH/NKV = 4
    const int tid = threadIdx.x;
    const int tx = tid & 15, ty = tid >> 4;

    // Load Q tile, pre-scaled by 1/sqrt(64)
    for (int f = tid; f < BQ * 16; f += 256) {
        int r = f >> 4, c = (f & 15) << 2;
        float4 v = *(const float4*)(Q + (size_t)(b * SS + qb * BQ + r) * DD + h * 64 + c);
        v.x *= 0.125f; v.y *= 0.125f; v.z *= 0.125f; v.w *= 0.125f;
        *(float4*)&Qs[r * LW + c] = v;
    }

    float m_i[4], l_i[4], acc[4][4];
#pragma unroll
    for (int i = 0; i < 4; i++) {
        m_i[i] = -1e30f; l_i[i] = 0.f;
#pragma unroll
        for (int j = 0; j < 4; j++) acc[i][j] = 0.f;
    }

    for (int kt = 0; kt < SS / BKV; kt++) {
        __syncthreads();   // protect Vs/Ks/Ms from previous iteration's readers
        for (int f = tid; f < BKV * 16; f += 256) {
            int r = f >> 4, c = (f & 15) << 2;
            size_t grow = (size_t)(b * SS + kt * BKV + r);
            *(float4*)&Ks[r * LW + c] = *(const float4*)(Km + grow * (NKV * DH) + kv * 64 + c);
            *(float4*)&Vs[r * LW + c] = *(const float4*)(Vm + grow * (NKV * DH) + kv * 64 + c);
        }
        if (tid < BKV)
            Ms[tid] = (1.0f - mask[b * SS + kt * BKV + tid]) * -1e9f;
        __syncthreads();

        // scores S = Q*K^T (4x4 microtile), vectorized over d
        float s[4][4];
#pragma unroll
        for (int i = 0; i < 4; i++)
#pragma unroll
            for (int j = 0; j < 4; j++) s[i][j] = 0.f;

#pragma unroll
        for (int d = 0; d < 64; d += 4) {
            float4 qa[4], kb[4];
#pragma unroll
            for (int i = 0; i < 4; i++) qa[i] = *(const float4*)&Qs[(ty * 4 + i) * LW + d];
#pragma unroll
            for (int j = 0; j < 4; j++) kb[j] = *(const float4*)&Ks[(tx * 4 + j) * LW + d];
#pragma unroll
            for (int i = 0; i < 4; i++)
#pragma unroll
                for (int j = 0; j < 4; j++)
                    s[i][j] += qa[i].x * kb[j].x + qa[i].y * kb[j].y
                             + qa[i].z * kb[j].z + qa[i].w * kb[j].w;
        }
#pragma unroll
        for (int i = 0; i < 4; i++)
#pragma unroll
            for (int j = 0; j < 4; j++) s[i][j] += Ms[tx * 4 + j];

        // streaming softmax per q-row (reduce across 16 tx lanes in half-warp)
#pragma unroll
        for (int i = 0; i < 4; i++) {
            float mt = fmaxf(fmaxf(s[i][0], s[i][1]), fmaxf(s[i][2], s[i][3]));
#pragma unroll
            for (int o = 8; o > 0; o >>= 1)
                mt = fmaxf(mt, __shfl_xor_sync(0xffffffffu, mt, o));
            float mn = fmaxf(m_i[i], mt);
            float corr = __expf(m_i[i] - mn);
            m_i[i] = mn;
            float rs = 0.f;
#pragma unroll
            for (int j = 0; j < 4; j++) {
                float p = __expf(s[i][j] - mn);
                s[i][j] = p; rs += p;
            }
#pragma unroll
            for (int o = 8; o > 0; o >>= 1)
                rs += __shfl_xor_sync(0xffffffffu, rs, o);
            l_i[i] = l_i[i] * corr + rs;
#pragma unroll
            for (int j = 0; j < 4; j++) acc[i][j] *= corr;
            float4 pv = make_float4(s[i][0], s[i][1], s[i][2], s[i][3]);
            *(float4*)&Ps[(ty * 4 + i) * LW + tx * 4] = pv;
        }
        __syncthreads();

        // O += P @ V
#pragma unroll 4
        for (int k = 0; k < BKV; k++) {
            float4 v4 = *(const float4*)&Vs[k * LW + tx * 4];
#pragma unroll
            for (int i = 0; i < 4; i++) {
                float p = Ps[(ty * 4 + i) * LW + k];
                acc[i][0] += p * v4.x; acc[i][1] += p * v4.y;
                acc[i][2] += p * v4.z; acc[i][3] += p * v4.w;
            }
        }
    }

    // normalize + write
#pragma unroll
    for (int i = 0; i < 4; i++) {
        float invl = 1.0f / l_i[i];
        size_t r = (size_t)(b * SS + qb * BQ + ty * 4 + i);
        float4 o = make_float4(acc[i][0] * invl, acc[i][1] * invl,
                               acc[i][2] * invl, acc[i][3] * invl);
        *(float4*)&O[r * DD + h * 64 + tx * 4] = o;
    }
}

// ---------------- launcher ----------------
extern "C" void kernel_launch(void* const* d_in, const int* in_sizes, int n_in,
                              void* d_out, int out_size)
{
    const float* hs   = (const float*)d_in[0];
    const float* mask = (const float*)d_in[1];
    const float* Wq   = (const float*)d_in[2];
    const float* bq   = (const float*)d_in[3];
    const float* Wk   = (const float*)d_in[4];
    const float* bk   = (const float*)d_in[5];
    const float* Wv   = (const float*)d_in[6];
    const float* bv   = (const float*)d_in[7];
    const float* Wo   = (const float*)d_in[8];
    const float* bo   = (const float*)d_in[9];
    float* out = (float*)d_out;

    float *q, *k, *v, *qr, *kr, *ao;
    cudaGetSymbolAddress((void**)&q,  g_q);
    cudaGetSymbolAddress((void**)&k,  g_k);
    cudaGetSymbolAddress((void**)&v,  g_v);
    cudaGetSymbolAddress((void**)&qr, g_qr);
    cudaGetSymbolAddress((void**)&kr, g_kr);
    cudaGetSymbolAddress((void**)&ao, g_ao);

    // QKV projections
    sgemm_bias<<<dim3(DD / GBN, MM / GBM), 256>>>(hs, Wq, bq, q, MM, DD, DD);
    sgemm_bias<<<dim3((NKV * DH) / GBN, MM / GBM), 256>>>(hs, Wk, bk, k, MM, NKV * DH, DD);
    sgemm_bias<<<dim3((NKV * DH) / GBN, MM / GBM), 256>>>(hs, Wv, bv, v, MM, NKV * DH, DD);

    // RoPE
    rope_kernel<<<(MM * NH * 32) / 256, 256>>>(q, qr, NH);
    rope_kernel<<<(MM * NKV * 32) / 256, 256>>>(k, kr, NKV);

    // attention
    cudaFuncSetAttribute(attn_kernel, cudaFuncAttributeMaxDynamicSharedMemorySize, ATTN_SMEM);
    attn_kernel<<<dim3(SS / BQ, NH, BB), 256, ATTN_SMEM>>>(qr, kr, v, mask, ao);

    // output projection
    sgemm_bias<<<dim3(DD / GBN, MM / GBM), 256>>>(ao, Wo, bo, out, MM, DD, DD);
}

// round 2
// speedup vs baseline: 4.1278x; 4.1278x over previous
#include <cuda_runtime.h>
#include <math.h>

// Problem constants
#define BB 2
#define SS 2048
#define DD 1024
#define NH 16
#define NKV 4
#define DH 64
#define MM (BB*SS)   // 4096

// ---------------- scratch (static device globals; no allocation) ----------------
__device__ float g_q [MM * DD];        // q proj  [4096,1024]
__device__ float g_k [MM * NKV*DH];    // k proj  [4096,256]
__device__ float g_v [MM * NKV*DH];    // v proj  [4096,256]
__device__ float g_qr[MM * DD];        // roped q
__device__ float g_kr[MM * NKV*DH];    // roped k
__device__ float g_ao[MM * DD];        // attention output [4096,1024]

// ---------------- helpers ----------------
__device__ __forceinline__ float f2tf(float x) {
    unsigned u;
    asm("cvt.rna.tf32.f32 %0, %1;" : "=r"(u) : "f"(x));
    return __uint_as_float(u);
}

__device__ __forceinline__ void mma8(float* d, const unsigned* a, const unsigned* b,
                                     const float* c) {
    asm volatile(
        "mma.sync.aligned.m16n8k8.row.col.f32.tf32.tf32.f32 "
        "{%0,%1,%2,%3}, {%4,%5,%6,%7}, {%8,%9}, {%10,%11,%12,%13};"
        : "=f"(d[0]), "=f"(d[1]), "=f"(d[2]), "=f"(d[3])
        : "r"(a[0]), "r"(a[1]), "r"(a[2]), "r"(a[3]),
          "r"(b[0]), "r"(b[1]),
          "f"(c[0]), "f"(c[1]), "f"(c[2]), "f"(c[3]));
}

// ---------------- tf32 tensor-core GEMM: C[M,N] = A[M,K] @ B[K,N] + bias ------
// BM=128 BN=128 BK=32, 256 threads (8 warps), warp tile 64x32 (4 m-tiles x 4 n-tiles)
#define TBM 128
#define TBN 128
#define TBK 32
#define ASTR 36    // (4*gr + tig) % 32 unique -> conflict-free A frag loads
#define BSTR 136   // (8*tig + gr) % 32 unique -> conflict-free B frag loads

__global__ __launch_bounds__(256)
void tgemm_bias(const float* __restrict__ A, const float* __restrict__ B,
                const float* __restrict__ bias, float* __restrict__ C,
                int M, int N, int K)
{
    __shared__ float As[TBM * ASTR];
    __shared__ float Bs[TBK * BSTR];

    const int tid  = threadIdx.x;
    const int lane = tid & 31;
    const int warp = tid >> 5;
    const int gr   = lane >> 2;
    const int tig  = lane & 3;
    const int warp_m = (warp & 1) * 64;
    const int warp_n = (warp >> 1) * 32;
    const int bm = blockIdx.y * TBM;
    const int bn = blockIdx.x * TBN;

    float acc[4][4][4];
#pragma unroll
    for (int mt = 0; mt < 4; mt++)
#pragma unroll
        for (int nt = 0; nt < 4; nt++)
#pragma unroll
            for (int i = 0; i < 4; i++) acc[mt][nt][i] = 0.f;

    float4 ra[4], rb[4];

    // prologue loads (k0 = 0)
#pragma unroll
    for (int i = 0; i < 4; i++) {
        int idx = tid + i * 256;
        int m = idx >> 3, c = (idx & 7) << 2;
        ra[i] = *(const float4*)(A + (size_t)(bm + m) * K + c);
        int kk = idx >> 5, n = (idx & 31) << 2;
        rb[i] = *(const float4*)(B + (size_t)kk * N + bn + n);
    }

    for (int k0 = 0; k0 < K; k0 += TBK) {
        // stage registers -> smem (with tf32 rounding)
#pragma unroll
        for (int i = 0; i < 4; i++) {
            int idx = tid + i * 256;
            int m = idx >> 3, c = (idx & 7) << 2;
            As[m * ASTR + c + 0] = f2tf(ra[i].x);
            As[m * ASTR + c + 1] = f2tf(ra[i].y);
            As[m * ASTR + c + 2] = f2tf(ra[i].z);
            As[m * ASTR + c + 3] = f2tf(ra[i].w);
            int kk = idx >> 5, n = (idx & 31) << 2;
            float4 t = make_float4(f2tf(rb[i].x), f2tf(rb[i].y),
                                   f2tf(rb[i].z), f2tf(rb[i].w));
            *(float4*)(&Bs[kk * BSTR + n]) = t;
        }
        __syncthreads();

        // prefetch next tile
        if (k0 + TBK < K) {
#pragma unroll
            for (int i = 0; i < 4; i++) {
                int idx = tid + i * 256;
                int m = idx >> 3, c = (idx & 7) << 2;
                ra[i] = *(const float4*)(A + (size_t)(bm + m) * K + k0 + TBK + c);
                int kk = idx >> 5, n = (idx & 31) << 2;
                rb[i] = *(const float4*)(B + (size_t)(k0 + TBK + kk) * N + bn + n);
            }
        }

        // compute 4 k-steps
#pragma unroll
        for (int ks = 0; ks < 4; ks++) {
            int kk = ks * 8;
            unsigned afr[4][4], bfr[4][2];
#pragma unroll
            for (int mt = 0; mt < 4; mt++) {
                int r0 = warp_m + mt * 16 + gr;
                afr[mt][0] = __float_as_uint(As[r0 * ASTR + kk + tig]);
                afr[mt][1] = __float_as_uint(As[(r0 + 8) * ASTR + kk + tig]);
                afr[mt][2] = __float_as_uint(As[r0 * ASTR + kk + tig + 4]);
                afr[mt][3] = __float_as_uint(As[(r0 + 8) * ASTR + kk + tig + 4]);
            }
#pragma unroll
            for (int nt = 0; nt < 4; nt++) {
                int c0 = warp_n + nt * 8 + gr;
                bfr[nt][0] = __float_as_uint(Bs[(kk + tig) * BSTR + c0]);
                bfr[nt][1] = __float_as_uint(Bs[(kk + tig + 4) * BSTR + c0]);
            }
#pragma unroll
            for (int mt = 0; mt < 4; mt++)
#pragma unroll
                for (int nt = 0; nt < 4; nt++)
                    mma8(acc[mt][nt], afr[mt], bfr[nt], acc[mt][nt]);
        }
        __syncthreads();
    }

    // epilogue
#pragma unroll
    for (int mt = 0; mt < 4; mt++) {
        int r0 = bm + warp_m + mt * 16 + gr;
#pragma unroll
        for (int nt = 0; nt < 4; nt++) {
            int c0 = bn + warp_n + nt * 8 + 2 * tig;
            float bx = bias[c0], by = bias[c0 + 1];
            float2 o0 = make_float2(acc[mt][nt][0] + bx, acc[mt][nt][1] + by);
            float2 o1 = make_float2(acc[mt][nt][2] + bx, acc[mt][nt][3] + by);
            *(float2*)(&C[(size_t)r0 * N + c0]) = o0;
            *(float2*)(&C[(size_t)(r0 + 8) * N + c0]) = o1;
        }
    }
}

// ---------------- RoPE: half-split rotation per head ----------------
__global__ void rope_kernel(const float* __restrict__ in, float* __restrict__ out,
                            int nHeads)
{
    int idx = blockIdx.x * blockDim.x + threadIdx.x;
    int total = MM * nHeads * 32;
    if (idx >= total) return;
    int i   = idx & 31;
    int h   = (idx >> 5) % nHeads;
    int row = idx / (nHeads * 32);
    int s   = row & (SS - 1);

    float ex  = -(float)(2 * i) / 64.0f;
    float inv = powf(10000.0f, ex);
    float ang = (float)s * inv;
    float sn, cs;
    sincosf(ang, &sn, &cs);

    int stride = nHeads * 64;
    const float* p = in  + (size_t)row * stride + h * 64;
    float*       q = out + (size_t)row * stride + h * 64;
    float x1 = p[i], x2 = p[i + 32];
    q[i]      = x1 * cs - x2 * sn;
    q[i + 32] = x1 * sn + x2 * cs;
}

// ---------------- flash attention with tf32 mma ----------------
// 64x64 tiles, 4 warps x 16 q-rows, streaming softmax on fragments
#define QSTR 68
#define KSTR 68
#define VSTR 72
#define PSTR 68
#define ATTN_SMEM ((64*QSTR + 64*KSTR + 64*VSTR + 64*PSTR + 64) * 4)

__global__ __launch_bounds__(128)
void attn_mma_kernel(const float* __restrict__ Q,    // [4096,1024] roped
                     const float* __restrict__ Km,   // [4096,256]  roped
                     const float* __restrict__ Vm,   // [4096,256]
                     const float* __restrict__ mask, // [B,S]
                     float* __restrict__ O)          // [4096,1024]
{
    extern __shared__ float sm[];
    float* Qs = sm;
    float* Ks = Qs + 64 * QSTR;
    float* Vs = Ks + 64 * KSTR;
    float* Ps = Vs + 64 * VSTR;
    float* Ms = Ps + 64 * PSTR;

    const int qb = blockIdx.x, h = blockIdx.y, b = blockIdx.z;
    const int kv = h >> 2;
    const int tid  = threadIdx.x;
    const int lane = tid & 31;
    const int warp = tid >> 5;
    const int gr   = lane >> 2;
    const int tig  = lane & 3;
    const int q0   = warp * 16;

    // load Q tile (scaled by 1/sqrt(64), tf32-rounded)
#pragma unroll
    for (int i = 0; i < 8; i++) {
        int idx = tid + i * 128;
        int r = idx >> 4, c = (idx & 15) << 2;
        float4 v = *(const float4*)(Q + (size_t)(b * SS + qb * 64 + r) * DD + h * 64 + c);
        float4 t = make_float4(f2tf(v.x * 0.125f), f2tf(v.y * 0.125f),
                               f2tf(v.z * 0.125f), f2tf(v.w * 0.125f));
        *(float4*)(&Qs[r * QSTR + c]) = t;
    }

    float o[8][4];
#pragma unroll
    for (int nt = 0; nt < 8; nt++)
#pragma unroll
        for (int i = 0; i < 4; i++) o[nt][i] = 0.f;
    float m0 = -1e30f, m1 = -1e30f, l0 = 0.f, l1 = 0.f;

    for (int kt = 0; kt < SS / 64; kt++) {
        __syncthreads();   // prev iter consumers done with Ks/Vs/Ms
#pragma unroll
        for (int i = 0; i < 8; i++) {
            int idx = tid + i * 128;
            int r = idx >> 4, c = (idx & 15) << 2;
            size_t grow = (size_t)(b * SS + kt * 64 + r);
            float4 kvv = *(const float4*)(Km + grow * (NKV * DH) + kv * 64 + c);
            float4 vvv = *(const float4*)(Vm + grow * (NKV * DH) + kv * 64 + c);
            *(float4*)(&Ks[r * KSTR + c]) = make_float4(f2tf(kvv.x), f2tf(kvv.y),
                                                        f2tf(kvv.z), f2tf(kvv.w));
            *(float4*)(&Vs[r * VSTR + c]) = make_float4(f2tf(vvv.x), f2tf(vvv.y),
                                                        f2tf(vvv.z), f2tf(vvv.w));
        }
        if (tid < 64)
            Ms[tid] = (1.0f - mask[b * SS + kt * 64 + tid]) * -1e9f;
        __syncthreads();

        // ---- S = Q @ K^T ----
        float s[8][4];
#pragma unroll
        for (int nt = 0; nt < 8; nt++)
#pragma unroll
            for (int i = 0; i < 4; i++) s[nt][i] = 0.f;

#pragma unroll
        for (int kk = 0; kk < 64; kk += 8) {
            unsigned a[4];
            a[0] = __float_as_uint(Qs[(q0 + gr) * QSTR + kk + tig]);
            a[1] = __float_as_uint(Qs[(q0 + gr + 8) * QSTR + kk + tig]);
            a[2] = __float_as_uint(Qs[(q0 + gr) * QSTR + kk + tig + 4]);
            a[3] = __float_as_uint(Qs[(q0 + gr + 8) * QSTR + kk + tig + 4]);
#pragma unroll
            for (int nt = 0; nt < 8; nt++) {
                unsigned bfr[2];
                bfr[0] = __float_as_uint(Ks[(nt * 8 + gr) * KSTR + kk + tig]);
                bfr[1] = __float_as_uint(Ks[(nt * 8 + gr) * KSTR + kk + tig + 4]);
                mma8(s[nt], a, bfr, s[nt]);
            }
        }

        // mask bias
#pragma unroll
        for (int nt = 0; nt < 8; nt++) {
            float mb0 = Ms[nt * 8 + 2 * tig], mb1 = Ms[nt * 8 + 2 * tig + 1];
            s[nt][0] += mb0; s[nt][1] += mb1;
            s[nt][2] += mb0; s[nt][3] += mb1;
        }

        // ---- streaming softmax (rows gr and gr+8 of this warp's 16) ----
        float mx0 = -1e30f, mx1 = -1e30f;
#pragma unroll
        for (int nt = 0; nt < 8; nt++) {
            mx0 = fmaxf(mx0, fmaxf(s[nt][0], s[nt][1]));
            mx1 = fmaxf(mx1, fmaxf(s[nt][2], s[nt][3]));
        }
        mx0 = fmaxf(mx0, __shfl_xor_sync(0xffffffffu, mx0, 1));
        mx0 = fmaxf(mx0, __shfl_xor_sync(0xffffffffu, mx0, 2));
        mx1 = fmaxf(mx1, __shfl_xor_sync(0xffffffffu, mx1, 1));
        mx1 = fmaxf(mx1, __shfl_xor_sync(0xffffffffu, mx1, 2));

        float mn0 = fmaxf(m0, mx0), mn1 = fmaxf(m1, mx1);
        float c0 = __expf(m0 - mn0), c1 = __expf(m1 - mn1);
        m0 = mn0; m1 = mn1;

        float rs0 = 0.f, rs1 = 0.f;
#pragma unroll
        for (int nt = 0; nt < 8; nt++) {
            s[nt][0] = __expf(s[nt][0] - mn0);
            s[nt][1] = __expf(s[nt][1] - mn0);
            s[nt][2] = __expf(s[nt][2] - mn1);
            s[nt][3] = __expf(s[nt][3] - mn1);
            rs0 += s[nt][0] + s[nt][1];
            rs1 += s[nt][2] + s[nt][3];
        }
        rs0 += __shfl_xor_sync(0xffffffffu, rs0, 1);
        rs0 += __shfl_xor_sync(0xffffffffu, rs0, 2);
        rs1 += __shfl_xor_sync(0xffffffffu, rs1, 1);
        rs1 += __shfl_xor_sync(0xffffffffu, rs1, 2);
        l0 = l0 * c0 + rs0;
        l1 = l1 * c1 + rs1;

#pragma unroll
        for (int nt = 0; nt < 8; nt++) {
            o[nt][0] *= c0; o[nt][1] *= c0;
            o[nt][2] *= c1; o[nt][3] *= c1;
            // P -> smem (warp-private rows)
            *(float2*)(&Ps[(q0 + gr) * PSTR + nt * 8 + 2 * tig]) =
                make_float2(s[nt][0], s[nt][1]);
            *(float2*)(&Ps[(q0 + gr + 8) * PSTR + nt * 8 + 2 * tig]) =
                make_float2(s[nt][2], s[nt][3]);
        }
        __syncwarp();

        // ---- O += P @ V ----
#pragma unroll
        for (int kk = 0; kk < 64; kk += 8) {
            unsigned a[4];
            a[0] = __float_as_uint(Ps[(q0 + gr) * PSTR + kk + tig]);
            a[1] = __float_as_uint(Ps[(q0 + gr + 8) * PSTR + kk + tig]);
            a[2] = __float_as_uint(Ps[(q0 + gr) * PSTR + kk + tig + 4]);
            a[3] = __float_as_uint(Ps[(q0 + gr + 8) * PSTR + kk + tig + 4]);
#pragma unroll
            for (int nt = 0; nt < 8; nt++) {
                unsigned bfr[2];
                bfr[0] = __float_as_uint(Vs[(kk + tig) * VSTR + nt * 8 + gr]);
                bfr[1] = __float_as_uint(Vs[(kk + tig + 4) * VSTR + nt * 8 + gr]);
                mma8(o[nt], a, bfr, o[nt]);
            }
        }
        __syncwarp();
    }

    // normalize + write
    float inv0 = 1.0f / l0, inv1 = 1.0f / l1;
    int rg = b * SS + qb * 64 + q0 + gr;
#pragma unroll
    for (int nt = 0; nt < 8; nt++) {
        int col = h * 64 + nt * 8 + 2 * tig;
        *(float2*)(&O[(size_t)rg * DD + col]) =
            make_float2(o[nt][0] * inv0, o[nt][1] * inv0);
        *(float2*)(&O[(size_t)(rg + 8) * DD + col]) =
            make_float2(o[nt][2] * inv1, o[nt][3] * inv1);
    }
}

// ---------------- launcher ----------------
extern "C" void kernel_launch(void* const* d_in, const int* in_sizes, int n_in,
                              void* d_out, int out_size)
{
    const float* hs   = (const float*)d_in[0];
    const float* mask = (const float*)d_in[1];
    const float* Wq   = (const float*)d_in[2];
    const float* bq   = (const float*)d_in[3];
    const float* Wk   = (const float*)d_in[4];
    const float* bk   = (const float*)d_in[5];
    const float* Wv   = (const float*)d_in[6];
    const float* bv   = (const float*)d_in[7];
    const float* Wo   = (const float*)d_in[8];
    const float* bo   = (const float*)d_in[9];
    float* out = (float*)d_out;

    float *q, *k, *v, *qr, *kr, *ao;
    cudaGetSymbolAddress((void**)&q,  g_q);
    cudaGetSymbolAddress((void**)&k,  g_k);
    cudaGetSymbolAddress((void**)&v,  g_v);
    cudaGetSymbolAddress((void**)&qr, g_qr);
    cudaGetSymbolAddress((void**)&kr, g_kr);
    cudaGetSymbolAddress((void**)&ao, g_ao);

    // QKV projections (tf32 tensor cores)
    tgemm_bias<<<dim3(DD / TBN, MM / TBM), 256>>>(hs, Wq, bq, q, MM, DD, DD);
    tgemm_bias<<<dim3((NKV * DH) / TBN, MM / TBM), 256>>>(hs, Wk, bk, k, MM, NKV * DH, DD);
    tgemm_bias<<<dim3((NKV * DH) / TBN, MM / TBM), 256>>>(hs, Wv, bv, v, MM, NKV * DH, DD);

    // RoPE
    rope_kernel<<<(MM * NH * 32) / 256, 256>>>(q, qr, NH);
    rope_kernel<<<(MM * NKV * 32) / 256, 256>>>(k, kr, NKV);

    // attention (tf32 tensor cores)
    cudaFuncSetAttribute(attn_mma_kernel, cudaFuncAttributeMaxDynamicSharedMemorySize, ATTN_SMEM);
    attn_mma_kernel<<<dim3(SS / 64, NH, BB), 128, ATTN_SMEM>>>(qr, kr, v, mask, ao);

    // output projection
    tgemm_bias<<<dim3(DD / TBN, MM / TBM), 256>>>(ao, Wo, bo, out, MM, DD, DD);
}

// round 3
// speedup vs baseline: 4.4145x; 1.0695x over previous
#include <cuda_runtime.h>
#include <math.h>

// Problem constants
#define BB 2
#define SS 2048
#define DD 1024
#define NH 16
#define NKV 4
#define DH 64
#define MM (BB*SS)   // 4096

// ---------------- scratch (static device globals; no allocation) ----------------
__device__ float g_q [MM * DD];        // q proj  [4096,1024]
__device__ float g_k [MM * NKV*DH];    // k proj  [4096,256]
__device__ float g_v [MM * NKV*DH];    // v proj  [4096,256]
__device__ float g_qr[MM * DD];        // roped q
__device__ float g_kr[MM * NKV*DH];    // roped k
__device__ float g_ao[MM * DD];        // attention output [4096,1024]

// ---------------- helpers ----------------
__device__ __forceinline__ float f2tf(float x) {
    unsigned u;
    asm("cvt.rna.tf32.f32 %0, %1;" : "=r"(u) : "f"(x));
    return __uint_as_float(u);
}

__device__ __forceinline__ void mma8(float* d, const unsigned* a, const unsigned* b,
                                     const float* c) {
    asm volatile(
        "mma.sync.aligned.m16n8k8.row.col.f32.tf32.tf32.f32 "
        "{%0,%1,%2,%3}, {%4,%5,%6,%7}, {%8,%9}, {%10,%11,%12,%13};"
        : "=f"(d[0]), "=f"(d[1]), "=f"(d[2]), "=f"(d[3])
        : "r"(a[0]), "r"(a[1]), "r"(a[2]), "r"(a[3]),
          "r"(b[0]), "r"(b[1]),
          "f"(c[0]), "f"(c[1]), "f"(c[2]), "f"(c[3]));
}

// ---------------- tf32 tensor-core GEMM: C[M,N] = A[M,K] @ B[K,N] + bias ------
// BM=128 BN=128 BK=32, 256 threads (8 warps), warp tile 64x32 (4 m x 4 n of 16x8)
#define TBM 128
#define TBN 128
#define TBK 32
#define ASTR 36
#define BSTR 136

__global__ __launch_bounds__(256)
void tgemm_bias(const float* __restrict__ A, const float* __restrict__ B,
                const float* __restrict__ bias, float* __restrict__ C,
                int M, int N, int K)
{
    __shared__ float As[TBM * ASTR];
    __shared__ float Bs[TBK * BSTR];

    const int tid  = threadIdx.x;
    const int lane = tid & 31;
    const int warp = tid >> 5;
    const int gr   = lane >> 2;
    const int tig  = lane & 3;
    const int warp_m = (warp & 1) * 64;
    const int warp_n = (warp >> 1) * 32;
    const int bm = blockIdx.y * TBM;
    const int bn = blockIdx.x * TBN;

    float acc[4][4][4];
#pragma unroll
    for (int mt = 0; mt < 4; mt++)
#pragma unroll
        for (int nt = 0; nt < 4; nt++)
#pragma unroll
            for (int i = 0; i < 4; i++) acc[mt][nt][i] = 0.f;

    float4 ra[4], rb[4];

#pragma unroll
    for (int i = 0; i < 4; i++) {
        int idx = tid + i * 256;
        int m = idx >> 3, c = (idx & 7) << 2;
        ra[i] = *(const float4*)(A + (size_t)(bm + m) * K + c);
        int kk = idx >> 5, n = (idx & 31) << 2;
        rb[i] = *(const float4*)(B + (size_t)kk * N + bn + n);
    }

    for (int k0 = 0; k0 < K; k0 += TBK) {
#pragma unroll
        for (int i = 0; i < 4; i++) {
            int idx = tid + i * 256;
            int m = idx >> 3, c = (idx & 7) << 2;
            As[m * ASTR + c + 0] = f2tf(ra[i].x);
            As[m * ASTR + c + 1] = f2tf(ra[i].y);
            As[m * ASTR + c + 2] = f2tf(ra[i].z);
            As[m * ASTR + c + 3] = f2tf(ra[i].w);
            int kk = idx >> 5, n = (idx & 31) << 2;
            float4 t = make_float4(f2tf(rb[i].x), f2tf(rb[i].y),
                                   f2tf(rb[i].z), f2tf(rb[i].w));
            *(float4*)(&Bs[kk * BSTR + n]) = t;
        }
        __syncthreads();

        if (k0 + TBK < K) {
#pragma unroll
            for (int i = 0; i < 4; i++) {
                int idx = tid + i * 256;
                int m = idx >> 3, c = (idx & 7) << 2;
                ra[i] = *(const float4*)(A + (size_t)(bm + m) * K + k0 + TBK + c);
                int kk = idx >> 5, n = (idx & 31) << 2;
                rb[i] = *(const float4*)(B + (size_t)(k0 + TBK + kk) * N + bn + n);
            }
        }

#pragma unroll
        for (int ks = 0; ks < 4; ks++) {
            int kk = ks * 8;
            unsigned afr[4][4], bfr[4][2];
#pragma unroll
            for (int mt = 0; mt < 4; mt++) {
                int r0 = warp_m + mt * 16 + gr;
                afr[mt][0] = __float_as_uint(As[r0 * ASTR + kk + tig]);
                afr[mt][1] = __float_as_uint(As[(r0 + 8) * ASTR + kk + tig]);
                afr[mt][2] = __float_as_uint(As[r0 * ASTR + kk + tig + 4]);
                afr[mt][3] = __float_as_uint(As[(r0 + 8) * ASTR + kk + tig + 4]);
            }
#pragma unroll
            for (int nt = 0; nt < 4; nt++) {
                int c0 = warp_n + nt * 8 + gr;
                bfr[nt][0] = __float_as_uint(Bs[(kk + tig) * BSTR + c0]);
                bfr[nt][1] = __float_as_uint(Bs[(kk + tig + 4) * BSTR + c0]);
            }
#pragma unroll
            for (int mt = 0; mt < 4; mt++)
#pragma unroll
                for (int nt = 0; nt < 4; nt++)
                    mma8(acc[mt][nt], afr[mt], bfr[nt], acc[mt][nt]);
        }
        __syncthreads();
    }

#pragma unroll
    for (int mt = 0; mt < 4; mt++) {
        int r0 = bm + warp_m + mt * 16 + gr;
#pragma unroll
        for (int nt = 0; nt < 4; nt++) {
            int c0 = bn + warp_n + nt * 8 + 2 * tig;
            float bx = bias[c0], by = bias[c0 + 1];
            float2 o0 = make_float2(acc[mt][nt][0] + bx, acc[mt][nt][1] + by);
            float2 o1 = make_float2(acc[mt][nt][2] + bx, acc[mt][nt][3] + by);
            *(float2*)(&C[(size_t)r0 * N + c0]) = o0;
            *(float2*)(&C[(size_t)(r0 + 8) * N + c0]) = o1;
        }
    }
}

// ---- merged K/V projection: blockIdx.x 0-1 -> K proj, 2-3 -> V proj ----
__global__ __launch_bounds__(256)
void tgemm_kv(const float* __restrict__ A,
              const float* __restrict__ WK, const float* __restrict__ bK,
              const float* __restrict__ WV, const float* __restrict__ bV,
              float* __restrict__ CK, float* __restrict__ CV,
              int M, int N, int K)
{
    __shared__ float As[TBM * ASTR];
    __shared__ float Bs[TBK * BSTR];

    const int tid  = threadIdx.x;
    const int lane = tid & 31;
    const int warp = tid >> 5;
    const int gr   = lane >> 2;
    const int tig  = lane & 3;
    const int warp_m = (warp & 1) * 64;
    const int warp_n = (warp >> 1) * 32;
    const int bm = blockIdx.y * TBM;
    const bool isV = blockIdx.x >= 2;
    const int bn = (blockIdx.x & 1) * TBN;
    const float* B    = isV ? WV : WK;
    const float* bias = isV ? bV : bK;
    float* C          = isV ? CV : CK;

    float acc[4][4][4];
#pragma unroll
    for (int mt = 0; mt < 4; mt++)
#pragma unroll
        for (int nt = 0; nt < 4; nt++)
#pragma unroll
            for (int i = 0; i < 4; i++) acc[mt][nt][i] = 0.f;

    float4 ra[4], rb[4];
#pragma unroll
    for (int i = 0; i < 4; i++) {
        int idx = tid + i * 256;
        int m = idx >> 3, c = (idx & 7) << 2;
        ra[i] = *(const float4*)(A + (size_t)(bm + m) * K + c);
        int kk = idx >> 5, n = (idx & 31) << 2;
        rb[i] = *(const float4*)(B + (size_t)kk * N + bn + n);
    }

    for (int k0 = 0; k0 < K; k0 += TBK) {
#pragma unroll
        for (int i = 0; i < 4; i++) {
            int idx = tid + i * 256;
            int m = idx >> 3, c = (idx & 7) << 2;
            As[m * ASTR + c + 0] = f2tf(ra[i].x);
            As[m * ASTR + c + 1] = f2tf(ra[i].y);
            As[m * ASTR + c + 2] = f2tf(ra[i].z);
            As[m * ASTR + c + 3] = f2tf(ra[i].w);
            int kk = idx >> 5, n = (idx & 31) << 2;
            float4 t = make_float4(f2tf(rb[i].x), f2tf(rb[i].y),
                                   f2tf(rb[i].z), f2tf(rb[i].w));
            *(float4*)(&Bs[kk * BSTR + n]) = t;
        }
        __syncthreads();

        if (k0 + TBK < K) {
#pragma unroll
            for (int i = 0; i < 4; i++) {
                int idx = tid + i * 256;
                int m = idx >> 3, c = (idx & 7) << 2;
                ra[i] = *(const float4*)(A + (size_t)(bm + m) * K + k0 + TBK + c);
                int kk = idx >> 5, n = (idx & 31) << 2;
                rb[i] = *(const float4*)(B + (size_t)(k0 + TBK + kk) * N + bn + n);
            }
        }

#pragma unroll
        for (int ks = 0; ks < 4; ks++) {
            int kk = ks * 8;
            unsigned afr[4][4], bfr[4][2];
#pragma unroll
            for (int mt = 0; mt < 4; mt++) {
                int r0 = warp_m + mt * 16 + gr;
                afr[mt][0] = __float_as_uint(As[r0 * ASTR + kk + tig]);
                afr[mt][1] = __float_as_uint(As[(r0 + 8) * ASTR + kk + tig]);
                afr[mt][2] = __float_as_uint(As[r0 * ASTR + kk + tig + 4]);
                afr[mt][3] = __float_as_uint(As[(r0 + 8) * ASTR + kk + tig + 4]);
            }
#pragma unroll
            for (int nt = 0; nt < 4; nt++) {
                int c0 = warp_n + nt * 8 + gr;
                bfr[nt][0] = __float_as_uint(Bs[(kk + tig) * BSTR + c0]);
                bfr[nt][1] = __float_as_uint(Bs[(kk + tig + 4) * BSTR + c0]);
            }
#pragma unroll
            for (int mt = 0; mt < 4; mt++)
#pragma unroll
                for (int nt = 0; nt < 4; nt++)
                    mma8(acc[mt][nt], afr[mt], bfr[nt], acc[mt][nt]);
        }
        __syncthreads();
    }

#pragma unroll
    for (int mt = 0; mt < 4; mt++) {
        int r0 = bm + warp_m + mt * 16 + gr;
#pragma unroll
        for (int nt = 0; nt < 4; nt++) {
            int c0 = bn + warp_n + nt * 8 + 2 * tig;
            float bx = bias[c0], by = bias[c0 + 1];
            float2 o0 = make_float2(acc[mt][nt][0] + bx, acc[mt][nt][1] + by);
            float2 o1 = make_float2(acc[mt][nt][2] + bx, acc[mt][nt][3] + by);
            *(float2*)(&C[(size_t)r0 * N + c0]) = o0;
            *(float2*)(&C[(size_t)(r0 + 8) * N + c0]) = o1;
        }
    }
}

// ---------------- RoPE (q and k merged in one launch) ----------------
__global__ void rope_all_kernel(const float* __restrict__ qin, float* __restrict__ qout,
                                const float* __restrict__ kin, float* __restrict__ kout)
{
    int idx = blockIdx.x * blockDim.x + threadIdx.x;
    const int qTotal = MM * NH * 32;
    const float* in; float* out; int nHeads;
    if (idx < qTotal) { in = qin; out = qout; nHeads = NH; }
    else { idx -= qTotal; in = kin; out = kout; nHeads = NKV; }

    int i   = idx & 31;
    int h   = (idx >> 5) % nHeads;
    int row = idx / (nHeads * 32);
    int s   = row & (SS - 1);

    float ex  = -(float)(2 * i) / 64.0f;
    float inv = powf(10000.0f, ex);
    float ang = (float)s * inv;
    float sn, cs;
    sincosf(ang, &sn, &cs);

    int stride = nHeads * 64;
    const float* p = in  + (size_t)row * stride + h * 64;
    float*       q = out + (size_t)row * stride + h * 64;
    float x1 = p[i], x2 = p[i + 32];
    q[i]      = x1 * cs - x2 * sn;
    q[i + 32] = x1 * sn + x2 * cs;
}

// ---------------- flash attention with tf32 mma: BQ=128, 8 warps ----------------
#define BQ 128
#define QSTR 68
#define KSTR 68
#define VSTR 72
#define PSTR 68
#define ATTN_SMEM ((BQ*QSTR + 64*KSTR + 64*VSTR + BQ*PSTR + 64) * 4)

__global__ __launch_bounds__(256, 2)
void attn_mma_kernel(const float* __restrict__ Q,    // [4096,1024] roped
                     const float* __restrict__ Km,   // [4096,256]  roped
                     const float* __restrict__ Vm,   // [4096,256]
                     const float* __restrict__ mask, // [B,S]
                     float* __restrict__ O)          // [4096,1024]
{
    extern __shared__ float sm[];
    float* Qs = sm;
    float* Ks = Qs + BQ * QSTR;
    float* Vs = Ks + 64 * KSTR;
    float* Ps = Vs + 64 * VSTR;
    float* Ms = Ps + BQ * PSTR;

    const int qb = blockIdx.x, h = blockIdx.y, b = blockIdx.z;
    const int kv = h >> 2;
    const int tid  = threadIdx.x;
    const int lane = tid & 31;
    const int warp = tid >> 5;
    const int gr   = lane >> 2;
    const int tig  = lane & 3;
    const int q0   = warp * 16;

    // load Q tile (scaled by 1/sqrt(64), tf32-rounded)
#pragma unroll
    for (int i = 0; i < 8; i++) {
        int idx = tid + i * 256;
        int r = idx >> 4, c = (idx & 15) << 2;
        float4 v = *(const float4*)(Q + (size_t)(b * SS + qb * BQ + r) * DD + h * 64 + c);
        float4 t = make_float4(f2tf(v.x * 0.125f), f2tf(v.y * 0.125f),
                               f2tf(v.z * 0.125f), f2tf(v.w * 0.125f));
        *(float4*)(&Qs[r * QSTR + c]) = t;
    }

    float o[8][4];
#pragma unroll
    for (int nt = 0; nt < 8; nt++)
#pragma unroll
        for (int i = 0; i < 4; i++) o[nt][i] = 0.f;
    float m0 = -1e30f, m1 = -1e30f, l0 = 0.f, l1 = 0.f;

    for (int kt = 0; kt < SS / 64; kt++) {
        __syncthreads();
#pragma unroll
        for (int i = 0; i < 4; i++) {
            int idx = tid + i * 256;
            int r = idx >> 4, c = (idx & 15) << 2;
            size_t grow = (size_t)(b * SS + kt * 64 + r);
            float4 kvv = *(const float4*)(Km + grow * (NKV * DH) + kv * 64 + c);
            float4 vvv = *(const float4*)(Vm + grow * (NKV * DH) + kv * 64 + c);
            *(float4*)(&Ks[r * KSTR + c]) = make_float4(f2tf(kvv.x), f2tf(kvv.y),
                                                        f2tf(kvv.z), f2tf(kvv.w));
            *(float4*)(&Vs[r * VSTR + c]) = make_float4(f2tf(vvv.x), f2tf(vvv.y),
                                                        f2tf(vvv.z), f2tf(vvv.w));
        }
        if (tid < 64)
            Ms[tid] = (1.0f - mask[b * SS + kt * 64 + tid]) * -1e9f;
        __syncthreads();

        // ---- S = Q @ K^T ----
        float s[8][4];
#pragma unroll
        for (int nt = 0; nt < 8; nt++)
#pragma unroll
            for (int i = 0; i < 4; i++) s[nt][i] = 0.f;

#pragma unroll
        for (int kk = 0; kk < 64; kk += 8) {
            unsigned a[4];
            a[0] = __float_as_uint(Qs[(q0 + gr) * QSTR + kk + tig]);
            a[1] = __float_as_uint(Qs[(q0 + gr + 8) * QSTR + kk + tig]);
            a[2] = __float_as_uint(Qs[(q0 + gr) * QSTR + kk + tig + 4]);
            a[3] = __float_as_uint(Qs[(q0 + gr + 8) * QSTR + kk + tig + 4]);
#pragma unroll
            for (int nt = 0; nt < 8; nt++) {
                unsigned bfr[2];
                bfr[0] = __float_as_uint(Ks[(nt * 8 + gr) * KSTR + kk + tig]);
                bfr[1] = __float_as_uint(Ks[(nt * 8 + gr) * KSTR + kk + tig + 4]);
                mma8(s[nt], a, bfr, s[nt]);
            }
        }

#pragma unroll
        for (int nt = 0; nt < 8; nt++) {
            float mb0 = Ms[nt * 8 + 2 * tig], mb1 = Ms[nt * 8 + 2 * tig + 1];
            s[nt][0] += mb0; s[nt][1] += mb1;
            s[nt][2] += mb0; s[nt][3] += mb1;
        }

        // ---- streaming softmax ----
        float mx0 = -1e30f, mx1 = -1e30f;
#pragma unroll
        for (int nt = 0; nt < 8; nt++) {
            mx0 = fmaxf(mx0, fmaxf(s[nt][0], s[nt][1]));
            mx1 = fmaxf(mx1, fmaxf(s[nt][2], s[nt][3]));
        }
        mx0 = fmaxf(mx0, __shfl_xor_sync(0xffffffffu, mx0, 1));
        mx0 = fmaxf(mx0, __shfl_xor_sync(0xffffffffu, mx0, 2));
        mx1 = fmaxf(mx1, __shfl_xor_sync(0xffffffffu, mx1, 1));
        mx1 = fmaxf(mx1, __shfl_xor_sync(0xffffffffu, mx1, 2));

        float mn0 = fmaxf(m0, mx0), mn1 = fmaxf(m1, mx1);
        float c0 = __expf(m0 - mn0), c1 = __expf(m1 - mn1);
        m0 = mn0; m1 = mn1;

        float rs0 = 0.f, rs1 = 0.f;
#pragma unroll
        for (int nt = 0; nt < 8; nt++) {
            s[nt][0] = __expf(s[nt][0] - mn0);
            s[nt][1] = __expf(s[nt][1] - mn0);
            s[nt][2] = __expf(s[nt][2] - mn1);
            s[nt][3] = __expf(s[nt][3] - mn1);
            rs0 += s[nt][0] + s[nt][1];
            rs1 += s[nt][2] + s[nt][3];
        }
        rs0 += __shfl_xor_sync(0xffffffffu, rs0, 1);
        rs0 += __shfl_xor_sync(0xffffffffu, rs0, 2);
        rs1 += __shfl_xor_sync(0xffffffffu, rs1, 1);
        rs1 += __shfl_xor_sync(0xffffffffu, rs1, 2);
        l0 = l0 * c0 + rs0;
        l1 = l1 * c1 + rs1;

#pragma unroll
        for (int nt = 0; nt < 8; nt++) {
            o[nt][0] *= c0; o[nt][1] *= c0;
            o[nt][2] *= c1; o[nt][3] *= c1;
            *(float2*)(&Ps[(q0 + gr) * PSTR + nt * 8 + 2 * tig]) =
                make_float2(s[nt][0], s[nt][1]);
            *(float2*)(&Ps[(q0 + gr + 8) * PSTR + nt * 8 + 2 * tig]) =
                make_float2(s[nt][2], s[nt][3]);
        }
        __syncwarp();

        // ---- O += P @ V ----
#pragma unroll
        for (int kk = 0; kk < 64; kk += 8) {
            unsigned a[4];
            a[0] = __float_as_uint(Ps[(q0 + gr) * PSTR + kk + tig]);
            a[1] = __float_as_uint(Ps[(q0 + gr + 8) * PSTR + kk + tig]);
            a[2] = __float_as_uint(Ps[(q0 + gr) * PSTR + kk + tig + 4]);
            a[3] = __float_as_uint(Ps[(q0 + gr + 8) * PSTR + kk + tig + 4]);
#pragma unroll
            for (int nt = 0; nt < 8; nt++) {
                unsigned bfr[2];
                bfr[0] = __float_as_uint(Vs[(kk + tig) * VSTR + nt * 8 + gr]);
                bfr[1] = __float_as_uint(Vs[(kk + tig + 4) * VSTR + nt * 8 + gr]);
                mma8(o[nt], a, bfr, o[nt]);
            }
        }
        __syncwarp();
    }

    // normalize + write
    float inv0 = 1.0f / l0, inv1 = 1.0f / l1;
    int rg = b * SS + qb * BQ + q0 + gr;
#pragma unroll
    for (int nt = 0; nt < 8; nt++) {
        int col = h * 64 + nt * 8 + 2 * tig;
        *(float2*)(&O[(size_t)rg * DD + col]) =
            make_float2(o[nt][0] * inv0, o[nt][1] * inv0);
        *(float2*)(&O[(size_t)(rg + 8) * DD + col]) =
            make_float2(o[nt][2] * inv1, o[nt][3] * inv1);
    }
}

// ---------------- launcher ----------------
extern "C" void kernel_launch(void* const* d_in, const int* in_sizes, int n_in,
                              void* d_out, int out_size)
{
    const float* hs   = (const float*)d_in[0];
    const float* mask = (const float*)d_in[1];
    const float* Wq   = (const float*)d_in[2];
    const float* bq   = (const float*)d_in[3];
    const float* Wk   = (const float*)d_in[4];
    const float* bk   = (const float*)d_in[5];
    const float* Wv   = (const float*)d_in[6];
    const float* bv   = (const float*)d_in[7];
    const float* Wo   = (const float*)d_in[8];
    const float* bo   = (const float*)d_in[9];
    float* out = (float*)d_out;

    float *q, *k, *v, *qr, *kr, *ao;
    cudaGetSymbolAddress((void**)&q,  g_q);
    cudaGetSymbolAddress((void**)&k,  g_k);
    cudaGetSymbolAddress((void**)&v,  g_v);
    cudaGetSymbolAddress((void**)&qr, g_qr);
    cudaGetSymbolAddress((void**)&kr, g_kr);
    cudaGetSymbolAddress((void**)&ao, g_ao);

    // projections (tf32 tensor cores)
    tgemm_bias<<<dim3(DD / TBN, MM / TBM), 256>>>(hs, Wq, bq, q, MM, DD, DD);
    tgemm_kv<<<dim3(4, MM / TBM), 256>>>(hs, Wk, bk, Wv, bv, k, v, MM, NKV * DH, DD);

    // RoPE (q + k in one launch)
    rope_all_kernel<<<(MM * (NH + NKV) * 32) / 256, 256>>>(q, qr, k, kr);

    // attention (tf32 tensor cores)
    cudaFuncSetAttribute(attn_mma_kernel, cudaFuncAttributeMaxDynamicSharedMemorySize, ATTN_SMEM);
    attn_mma_kernel<<<dim3(SS / BQ, NH, BB), 256, ATTN_SMEM>>>(qr, kr, v, mask, ao);

    // output projection
    tgemm_bias<<<dim3(DD / TBN, MM / TBM), 256>>>(ao, Wo, bo, out, MM, DD, DD);
}